// round 15
// baseline (speedup 1.0000x reference)
#include <cuda_runtime.h>

// Problem dims (fixed by setup_inputs)
#define DD 2048      // D
#define OO 8192      // O
#define TT 4096      // T

#define WR_PARTS 128 // word-dim split for stage 1 (16 words per tile)
#define V_PARTS  32  // d-dim split for stage 2 (64 d per tile)

// Scratch (allocation-free rule: __device__ globals; zero-initialized at load)
__device__ float g_part_wr[WR_PARTS * DD];   // 1 MB
__device__ float g_part_v[V_PARTS * OO];     // 1 MB
__device__ float g_v[OO];                    // 32 KB

// ---------------------------------------------------------------------------
// K1: partial weighted row-sums of x.
// grid = (8 col-tiles, 128 word-tiles of 16), block = 256 -> 1024 blocks
// (~7 blocks/SM; the 512-block version measured occ 40.6%, grid-limited).
// 16 fully-unrolled independent loads per thread.
// wr[d] = sum_{word>=1} hrf[DD-word] * x[word,d]
// ---------------------------------------------------------------------------
__global__ __launch_bounds__(256)
void k1_partial_wr(const float* __restrict__ x, const float* __restrict__ hrf) {
    __shared__ float s_c[16];
    const int col = blockIdx.x * 256 + threadIdx.x;
    const int w0  = blockIdx.y * 16;

    if (threadIdx.x < 16) {
        int word = w0 + threadIdx.x;
        s_c[threadIdx.x] = (word >= 1) ? hrf[DD - word] : 0.0f;  // word 0 -> 0
    }
    __syncthreads();

    float acc = 0.0f;
    #pragma unroll
    for (int i = 0; i < 16; ++i) {
        acc = fmaf(s_c[i], x[(size_t)(w0 + i) * DD + col], acc);
    }
    g_part_wr[blockIdx.y * DD + col] = acc;
}

// ---------------------------------------------------------------------------
// K2: partial GEMV v = wr @ weights, wr-reduction fused as prologue.
// grid = (32 o-tiles, 32 d-tiles of 64), block = 256 -> 1024 blocks
// (vs 512 before: shorter tail, more warps hiding the 32KB-stride latency).
// Prologue: threads 0..63 finalize one wr element each from the 128
// L2-resident partials.
// ---------------------------------------------------------------------------
__global__ __launch_bounds__(256)
void k2_partial_v(const float* __restrict__ weights) {
    __shared__ float s_wr[64];
    const int o  = blockIdx.x * 256 + threadIdx.x;
    const int d0 = blockIdx.y * 64;

    if (threadIdx.x < 64) {
        float w = 0.0f;
        #pragma unroll
        for (int p = 0; p < WR_PARTS; ++p)
            w += g_part_wr[p * DD + d0 + threadIdx.x];
        s_wr[threadIdx.x] = w;
    }
    __syncthreads();

    float acc = 0.0f;
    const float* __restrict__ wp = weights + (size_t)d0 * OO + o;
    #pragma unroll 16
    for (int i = 0; i < 64; ++i) {
        acc = fmaf(s_wr[i], wp[(size_t)i * OO], acc);
    }
    g_part_v[blockIdx.y * OO + o] = acc;
}

// K2r: reduce 32 partials -> g_v. grid = 32, block = 256. (tiny, L2-resident)
__global__ __launch_bounds__(256)
void k2_reduce_v() {
    const int o = blockIdx.x * 256 + threadIdx.x;
    float acc = 0.0f;
    #pragma unroll
    for (int p = 0; p < V_PARTS; ++p) acc += g_part_v[p * OO + o];
    g_v[o] = acc;
}

// ---------------------------------------------------------------------------
// K3: out[t,o] = w_times_init[t,o] + v[o] + bias[t].
// Byte-identical to the measured-best 38.1us form: one block per half-row,
// MLP=4 front-batched streaming loads, v/bias L1-hot.
// ---------------------------------------------------------------------------
__global__ __launch_bounds__(256)
void k3_broadcast_add(const float4* __restrict__ w_init,
                      const float* __restrict__ bias,
                      float4* __restrict__ out) {
    const int t    = blockIdx.x >> 1;
    const int half = blockIdx.x & 1;
    const size_t base = (size_t)blockIdx.x * 1024 + threadIdx.x;

    const float b = __ldg(&bias[t]);

    const float4 w0 = __ldcs(&w_init[base]);
    const float4 w1 = __ldcs(&w_init[base + 256]);
    const float4 w2 = __ldcs(&w_init[base + 512]);
    const float4 w3 = __ldcs(&w_init[base + 768]);

    const float4* __restrict__ vp =
        reinterpret_cast<const float4*>(g_v) + half * 1024 + threadIdx.x;
    const float4 v0 = __ldg(&vp[0]);
    const float4 v1 = __ldg(&vp[256]);
    const float4 v2 = __ldg(&vp[512]);
    const float4 v3 = __ldg(&vp[768]);

    float4 r0, r1, r2, r3;
    r0.x = w0.x + v0.x + b; r0.y = w0.y + v0.y + b;
    r0.z = w0.z + v0.z + b; r0.w = w0.w + v0.w + b;
    r1.x = w1.x + v1.x + b; r1.y = w1.y + v1.y + b;
    r1.z = w1.z + v1.z + b; r1.w = w1.w + v1.w + b;
    r2.x = w2.x + v2.x + b; r2.y = w2.y + v2.y + b;
    r2.z = w2.z + v2.z + b; r2.w = w2.w + v2.w + b;
    r3.x = w3.x + v3.x + b; r3.y = w3.y + v3.y + b;
    r3.z = w3.z + v3.z + b; r3.w = w3.w + v3.w + b;

    __stcs(&out[base],       r0);
    __stcs(&out[base + 256], r1);
    __stcs(&out[base + 512], r2);
    __stcs(&out[base + 768], r3);
}

// ---------------------------------------------------------------------------
// Input order (metadata): x[D*D], hrf_weight[D], weights[D*O], bias[T],
//                         w_times_init[T*O].  Output: float32 [T*O].
// ---------------------------------------------------------------------------
extern "C" void kernel_launch(void* const* d_in, const int* in_sizes, int n_in,
                              void* d_out, int out_size) {
    const float* x      = (const float*)d_in[0];
    const float* hrf    = (const float*)d_in[1];
    const float* wts    = (const float*)d_in[2];
    const float* bias   = (const float*)d_in[3];
    const float* w_init = (const float*)d_in[4];
    float* out = (float*)d_out;

    k1_partial_wr<<<dim3(DD / 256, WR_PARTS), 256>>>(x, hrf);
    k2_partial_v<<<dim3(OO / 256, V_PARTS), 256>>>(wts);
    k2_reduce_v<<<OO / 256, 256>>>();
    k3_broadcast_add<<<TT * 2, 256>>>((const float4*)w_init, bias, (float4*)out);
}

// round 17
// speedup vs baseline: 1.0580x; 1.0580x over previous
#include <cuda_runtime.h>

// Problem dims (fixed by setup_inputs)
#define DD 2048      // D
#define OO 8192      // O
#define TT 4096      // T

#define WR_PARTS 64  // word-dim split for stage 1 (32 words per tile)
#define V_PARTS  16  // d-dim split for stage 2 (128 d per tile)

// Scratch (allocation-free rule: __device__ globals)
__device__ float g_part_wr[WR_PARTS * DD];   // 512 KB
__device__ float g_v[OO];                    // 32 KB (RED-accumulated)

// ---------------------------------------------------------------------------
// K1: partial weighted row-sums of x.  (body = measured-best R5 form)
// grid = (8 col-tiles, 64 word-tiles), block = 256. 32 words/tile, full unroll.
// wr[d] = sum_{word>=1} hrf[DD-word] * x[word,d]
// Blocks with by==0 also re-zero g_v for this replay; k1 completes before k2
// starts (stream order), so k2's RED adds never race the zeroing.
// ---------------------------------------------------------------------------
__global__ __launch_bounds__(256)
void k1_partial_wr(const float* __restrict__ x, const float* __restrict__ hrf) {
    __shared__ float s_c[32];
    const int col = blockIdx.x * 256 + threadIdx.x;
    const int w0  = blockIdx.y * 32;

    if (blockIdx.y == 0) {
        #pragma unroll
        for (int j = 0; j < 4; ++j)
            g_v[blockIdx.x * 1024 + j * 256 + threadIdx.x] = 0.0f;
    }
    if (threadIdx.x < 32) {
        int word = w0 + threadIdx.x;
        s_c[threadIdx.x] = (word >= 1) ? hrf[DD - word] : 0.0f;  // word 0 -> 0
    }
    __syncthreads();

    float acc = 0.0f;
    #pragma unroll
    for (int i = 0; i < 32; ++i) {
        acc = fmaf(s_c[i], x[(size_t)(w0 + i) * DD + col], acc);
    }
    g_part_wr[blockIdx.y * DD + col] = acc;
}

// ---------------------------------------------------------------------------
// K2: partial GEMV v = wr @ weights, wr-reduce fused as prologue.
// (prologue + mainloop = measured-best R5 form)
// Epilogue: fire-and-forget global float add into g_v (RED.ADD.F32) —
// replaces both the g_part_v buffer and the k2_reduce_v launch (~4.8us
// launch floor). 16 adds per element spread over k2's runtime.
// grid = (32 o-tiles, 16 d-tiles of 128), block = 256.
// ---------------------------------------------------------------------------
__global__ __launch_bounds__(256)
void k2_partial_v(const float* __restrict__ weights) {
    __shared__ float s_wr[128];
    const int o  = blockIdx.x * 256 + threadIdx.x;
    const int d0 = blockIdx.y * 128;

    if (threadIdx.x < 128) {          // fused wr-reduce (L2-resident partials)
        float w = 0.0f;
        #pragma unroll
        for (int p = 0; p < WR_PARTS; ++p)
            w += g_part_wr[p * DD + d0 + threadIdx.x];
        s_wr[threadIdx.x] = w;
    }
    __syncthreads();

    float acc = 0.0f;
    const float* __restrict__ wp = weights + (size_t)d0 * OO + o;
    #pragma unroll 16
    for (int i = 0; i < 128; ++i) {
        acc = fmaf(s_wr[i], wp[(size_t)i * OO], acc);
    }
    atomicAdd(&g_v[o], acc);          // result unused -> emitted as RED
}

// ---------------------------------------------------------------------------
// K3: out[t,o] = w_times_init[t,o] + v[o] + bias[t].
// Byte-identical to the measured-best 38.1us form: one block per half-row,
// MLP=4 front-batched streaming loads, v/bias L1-hot.
// ---------------------------------------------------------------------------
__global__ __launch_bounds__(256)
void k3_broadcast_add(const float4* __restrict__ w_init,
                      const float* __restrict__ bias,
                      float4* __restrict__ out) {
    const int t    = blockIdx.x >> 1;
    const int half = blockIdx.x & 1;
    const size_t base = (size_t)blockIdx.x * 1024 + threadIdx.x;

    const float b = __ldg(&bias[t]);

    const float4 w0 = __ldcs(&w_init[base]);
    const float4 w1 = __ldcs(&w_init[base + 256]);
    const float4 w2 = __ldcs(&w_init[base + 512]);
    const float4 w3 = __ldcs(&w_init[base + 768]);

    const float4* __restrict__ vp =
        reinterpret_cast<const float4*>(g_v) + half * 1024 + threadIdx.x;
    const float4 v0 = __ldg(&vp[0]);
    const float4 v1 = __ldg(&vp[256]);
    const float4 v2 = __ldg(&vp[512]);
    const float4 v3 = __ldg(&vp[768]);

    float4 r0, r1, r2, r3;
    r0.x = w0.x + v0.x + b; r0.y = w0.y + v0.y + b;
    r0.z = w0.z + v0.z + b; r0.w = w0.w + v0.w + b;
    r1.x = w1.x + v1.x + b; r1.y = w1.y + v1.y + b;
    r1.z = w1.z + v1.z + b; r1.w = w1.w + v1.w + b;
    r2.x = w2.x + v2.x + b; r2.y = w2.y + v2.y + b;
    r2.z = w2.z + v2.z + b; r2.w = w2.w + v2.w + b;
    r3.x = w3.x + v3.x + b; r3.y = w3.y + v3.y + b;
    r3.z = w3.z + v3.z + b; r3.w = w3.w + v3.w + b;

    __stcs(&out[base],       r0);
    __stcs(&out[base + 256], r1);
    __stcs(&out[base + 512], r2);
    __stcs(&out[base + 768], r3);
}

// ---------------------------------------------------------------------------
// Input order (metadata): x[D*D], hrf_weight[D], weights[D*O], bias[T],
//                         w_times_init[T*O].  Output: float32 [T*O].
// ---------------------------------------------------------------------------
extern "C" void kernel_launch(void* const* d_in, const int* in_sizes, int n_in,
                              void* d_out, int out_size) {
    const float* x      = (const float*)d_in[0];
    const float* hrf    = (const float*)d_in[1];
    const float* wts    = (const float*)d_in[2];
    const float* bias   = (const float*)d_in[3];
    const float* w_init = (const float*)d_in[4];
    float* out = (float*)d_out;

    k1_partial_wr<<<dim3(DD / 256, WR_PARTS), 256>>>(x, hrf);
    k2_partial_v<<<dim3(OO / 256, V_PARTS), 256>>>(wts);
    k3_broadcast_add<<<TT * 2, 256>>>((const float4*)w_init, bias, (float4*)out);
}